// round 9
// baseline (speedup 1.0000x reference)
#include <cuda_runtime.h>
#include <math.h>
#include <stdint.h>

#define N_NODES 20000
#define K_IN    8710
#define K_PAD   8712          // g_Wt row stride (16B aligned)
#define H_DIM   128
#define C_DIM   70

// ---- scratch (static device globals; no allocation allowed) ----
__device__ float g_h[(size_t)N_NODES * H_DIM];    // x@W1, then relu(agg+b1)
__device__ float g_agg[(size_t)N_NODES * H_DIM];  // layer-1 aggregation
__device__ float g_z[(size_t)N_NODES * C_DIM];    // h1@W2
__device__ float g_Wt[(size_t)H_DIM * K_PAD];     // W1^T, tf32-rounded, n-major
__device__ int   g_deg[N_NODES];
__device__ float g_dinv[N_NODES];

// ---------------------------------------------------------------------------
// degree / normalization
// ---------------------------------------------------------------------------
__global__ void k_zero_deg() {
    int i = blockIdx.x * blockDim.x + threadIdx.x;
    if (i < N_NODES) g_deg[i] = 0;
}

__global__ void k_count_deg(const int* __restrict__ edges, int E) {
    int e = blockIdx.x * blockDim.x + threadIdx.x;
    if (e < E) atomicAdd(&g_deg[edges[E + e]], 1);   // dst
}

__global__ void k_dinv() {
    int i = blockIdx.x * blockDim.x + threadIdx.x;
    if (i < N_NODES) g_dinv[i] = rsqrtf((float)(g_deg[i] + 1));  // +1 self loop
}

// ---------------------------------------------------------------------------
// W1 [K_IN x 128] -> g_Wt [128 x K_PAD], transposed + tf32-rounded + zero-pad
// ---------------------------------------------------------------------------
__global__ __launch_bounds__(256) void k_transpose(const float* __restrict__ W1) {
    __shared__ float t[32][33];
    int kb = blockIdx.x * 32;
    int hb = blockIdx.y * 32;
    int tx = threadIdx.x & 31;
    int ty = threadIdx.x >> 5;     // 0..7
#pragma unroll
    for (int i = 0; i < 4; i++) {
        int k = kb + ty + i * 8;
        if (k < K_IN) t[ty + i * 8][tx] = W1[(size_t)k * H_DIM + hb + tx];
    }
    __syncthreads();
#pragma unroll
    for (int i = 0; i < 4; i++) {
        int h = hb + ty + i * 8;
        int k = kb + tx;
        if (k < K_PAD) {
            float v = 0.f;
            if (k < K_IN) {
                unsigned u;
                asm("cvt.rna.tf32.f32 %0, %1;" : "=r"(u) : "f"(t[tx][ty + i * 8]));
                v = __uint_as_float(u);
            }
            g_Wt[(size_t)h * K_PAD + k] = v;
        }
    }
}

// ---------------------------------------------------------------------------
// zero-init g_h / g_agg rows of the split-K tiles (rows 18944..19999)
// ---------------------------------------------------------------------------
#define SPLIT_ROW0 18944
__global__ void k_zero_tail() {
    int idx = blockIdx.x * blockDim.x + threadIdx.x;   // float4 slots
    int total = (N_NODES - SPLIT_ROW0) * 32;
    if (idx >= total) return;
    float4 z = make_float4(0.f, 0.f, 0.f, 0.f);
    *reinterpret_cast<float4*>(g_h   + (size_t)SPLIT_ROW0 * H_DIM + idx * 4) = z;
    *reinterpret_cast<float4*>(g_agg + (size_t)SPLIT_ROW0 * H_DIM + idx * 4) = z;
}

// ---------------------------------------------------------------------------
// GEMM1, tf32 HMMA, ldmatrix fragments, BK=32, 3-stage cp.async pipeline.
//   bid 0..147   : full tiles, chunks [0,273), direct-store epilogue
//   bid 148..291 : tiles 148..156 split-K x16 (~17 chunks), red.add epilogue
// BM=128, BN=128, 256 threads = 8 warps (4m x 2n), warp tile 32x64.
// A smem: [128 rows][36 words] K-major;  B smem: [128 n][36 words] (W^T rows).
// ---------------------------------------------------------------------------
#define NCH32     ((K_IN + 31) / 32)   // 273
#define G1_STAGES 3
#define G1_BM 128
#define N_FULL    148
#define N_SPLITS  16
#define RS 36                                    // row stride in words
#define A_BYTES (128 * RS * 4)                   // 18432
#define STAGE_BYTES (2 * A_BYTES)                // 36864
#define G1_SMEM_BYTES (G1_STAGES * STAGE_BYTES)  // 110592
#define TRUNC_COMP 1.00034f

__device__ __forceinline__ unsigned smem_u32(const void* p) {
    unsigned a;
    asm("{ .reg .u64 t; cvta.to.shared.u64 t, %1; cvt.u32.u64 %0, t; }"
        : "=r"(a) : "l"(p));
    return a;
}

__global__ __launch_bounds__(256, 2) void k_gemm1_tc(const float* __restrict__ X) {
    extern __shared__ float sm[];

    const int tid  = threadIdx.x;
    const int warp = tid >> 5;
    const int lane = tid & 31;
    const int gid  = lane >> 2;
    const int tig  = lane & 3;
    const int warp_m = warp >> 1;   // 0..3
    const int warp_n = warp & 1;    // 0..1
    const unsigned sm_base = smem_u32(sm);

    // ---- work assignment ----
    int tile, c0, c_end;
    bool direct;
    if (blockIdx.x < N_FULL) {
        tile = blockIdx.x; c0 = 0; c_end = NCH32; direct = true;
    } else {
        int t = blockIdx.x - N_FULL;
        tile = N_FULL + t / N_SPLITS;
        int s = t % N_SPLITS;
        const int base = NCH32 / N_SPLITS;           // 17
        const int rem  = NCH32 % N_SPLITS;           // 1
        c0    = s * base + (s < rem ? s : rem);
        c_end = c0 + base + (s < rem ? 1 : 0);
        direct = false;
    }
    const int m0 = tile * G1_BM;

    // ---- per-lane ldmatrix base offsets (bytes, within stage) ----
    // A: mat j = lane>>3:  row group = (j&1)*8, k half = (j>>1)*4
    const unsigned a_lane_off =
        (unsigned)((warp_m * 32 + ((lane >> 3) & 1) * 8 + (lane & 7)) * (RS * 4)
                   + (lane >> 4) * 16);
    // B: mat j: k half = (j&1)*4, n group = (j>>1)*8
    const unsigned b_lane_off =
        (unsigned)((warp_n * 64 + ((lane >> 4) & 1) * 8 + (lane & 7)) * (RS * 4)
                   + ((lane >> 3) & 1) * 16);

    float acc[2][8][4];
#pragma unroll
    for (int i = 0; i < 2; i++)
#pragma unroll
        for (int j = 0; j < 8; j++)
#pragma unroll
            for (int t = 0; t < 4; t++) acc[i][j][t] = 0.f;

#define LOAD_STAGE(c)                                                             \
    {                                                                             \
        const unsigned a_u = sm_base + (unsigned)((c) % G1_STAGES) * STAGE_BYTES; \
        const unsigned b_u = a_u + A_BYTES;                                       \
        const int k0 = (c) * 32;                                                  \
        const bool inr = (c) < c_end;                                             \
        _Pragma("unroll")                                                         \
        for (int i = 0; i < 8; i++) {                                             \
            int p = tid + i * 256;                                                \
            int row = p >> 4;                                                     \
            int kp  = (p & 15) * 2;                                               \
            int gm = m0 + row, gk = k0 + kp;                                      \
            int ok = (inr && gm < N_NODES && gk + 1 < K_IN) ? 8 : 0;              \
            int gmc = gm < N_NODES ? gm : N_NODES - 1;                            \
            int gkc = gk + 1 < K_IN ? gk : 0;                                     \
            const float* src = X + (size_t)gmc * K_IN + gkc;                      \
            unsigned dst = a_u + (row * RS + kp) * 4;                             \
            asm volatile("cp.async.ca.shared.global [%0], [%1], 8, %2;"           \
                         :: "r"(dst), "l"(src), "r"(ok));                         \
        }                                                                         \
        _Pragma("unroll")                                                         \
        for (int i = 0; i < 4; i++) {                                             \
            int q = tid + i * 256;                                                \
            int row = q >> 3;                                                     \
            int kc  = (q & 7) * 4;                                                \
            int gk = k0 + kc;                                                     \
            int ok = (inr && gk + 3 < K_PAD) ? 16 : 0;                            \
            int gkc = gk + 3 < K_PAD ? gk : 0;                                    \
            const float* src = g_Wt + (size_t)row * K_PAD + gkc;                  \
            unsigned dst = b_u + (row * RS + kc) * 4;                             \
            asm volatile("cp.async.cg.shared.global [%0], [%1], 16, %2;"          \
                         :: "r"(dst), "l"(src), "r"(ok));                         \
        }                                                                         \
        asm volatile("cp.async.commit_group;");                                   \
    }

    LOAD_STAGE(c0);
    LOAD_STAGE(c0 + 1);

    for (int c = c0; c < c_end; ++c) {
        asm volatile("cp.async.wait_group 1;");
        __syncthreads();

        LOAD_STAGE(c + 2);

        const unsigned sa = sm_base + (unsigned)(c % G1_STAGES) * STAGE_BYTES;
        const unsigned a_base = sa + a_lane_off;
        const unsigned b_base = sa + A_BYTES + b_lane_off;

#pragma unroll
        for (int ks = 0; ks < 4; ks++) {
            unsigned af[2][4];
            unsigned bf[8][2];
#pragma unroll
            for (int mt = 0; mt < 2; mt++) {
                asm volatile(
                    "ldmatrix.sync.aligned.m8n8.x4.shared.b16 {%0,%1,%2,%3}, [%4];"
                    : "=r"(af[mt][0]), "=r"(af[mt][1]),
                      "=r"(af[mt][2]), "=r"(af[mt][3])
                    : "r"(a_base + mt * (16 * RS * 4) + ks * 32));
            }
#pragma unroll
            for (int p = 0; p < 4; p++) {
                asm volatile(
                    "ldmatrix.sync.aligned.m8n8.x4.shared.b16 {%0,%1,%2,%3}, [%4];"
                    : "=r"(bf[2 * p][0]), "=r"(bf[2 * p][1]),
                      "=r"(bf[2 * p + 1][0]), "=r"(bf[2 * p + 1][1])
                    : "r"(b_base + p * (16 * RS * 4) + ks * 32));
            }
#pragma unroll
            for (int mt = 0; mt < 2; mt++)
#pragma unroll
                for (int nt = 0; nt < 8; nt++) {
                    asm volatile(
                        "mma.sync.aligned.m16n8k8.row.col.f32.tf32.tf32.f32 "
                        "{%0,%1,%2,%3}, {%4,%5,%6,%7}, {%8,%9}, {%0,%1,%2,%3};"
                        : "+f"(acc[mt][nt][0]), "+f"(acc[mt][nt][1]),
                          "+f"(acc[mt][nt][2]), "+f"(acc[mt][nt][3])
                        : "r"(af[mt][0]), "r"(af[mt][1]), "r"(af[mt][2]), "r"(af[mt][3]),
                          "r"(bf[nt][0]), "r"(bf[nt][1]));
                }
        }
    }
#undef LOAD_STAGE

    // epilogue: truncation compensation + fused agg-init (g_agg = h * dinv^2)
#pragma unroll
    for (int mt = 0; mt < 2; mt++) {
        int r0 = m0 + warp_m * 32 + mt * 16 + gid;
        int r1 = r0 + 8;
        float s0 = 0.f, s1 = 0.f;
        if (r0 < N_NODES) { float dv = g_dinv[r0]; s0 = dv * dv; }
        if (r1 < N_NODES) { float dv = g_dinv[r1]; s1 = dv * dv; }
#pragma unroll
        for (int nt = 0; nt < 8; nt++) {
            int col = warp_n * 64 + nt * 8 + tig * 2;
            float h0 = acc[mt][nt][0] * TRUNC_COMP;
            float h1 = acc[mt][nt][1] * TRUNC_COMP;
            float h2 = acc[mt][nt][2] * TRUNC_COMP;
            float h3 = acc[mt][nt][3] * TRUNC_COMP;
            if (direct) {
                if (r0 < N_NODES) {
                    *reinterpret_cast<float2*>(g_h + (size_t)r0 * H_DIM + col) =
                        make_float2(h0, h1);
                    *reinterpret_cast<float2*>(g_agg + (size_t)r0 * H_DIM + col) =
                        make_float2(h0 * s0, h1 * s0);
                }
                if (r1 < N_NODES) {
                    *reinterpret_cast<float2*>(g_h + (size_t)r1 * H_DIM + col) =
                        make_float2(h2, h3);
                    *reinterpret_cast<float2*>(g_agg + (size_t)r1 * H_DIM + col) =
                        make_float2(h2 * s1, h3 * s1);
                }
            } else {
                if (r0 < N_NODES) {
                    asm volatile("red.global.add.v2.f32 [%0], {%1,%2};"
                                 :: "l"(g_h + (size_t)r0 * H_DIM + col),
                                    "f"(h0), "f"(h1) : "memory");
                    asm volatile("red.global.add.v2.f32 [%0], {%1,%2};"
                                 :: "l"(g_agg + (size_t)r0 * H_DIM + col),
                                    "f"(h0 * s0), "f"(h1 * s0) : "memory");
                }
                if (r1 < N_NODES) {
                    asm volatile("red.global.add.v2.f32 [%0], {%1,%2};"
                                 :: "l"(g_h + (size_t)r1 * H_DIM + col),
                                    "f"(h2), "f"(h3) : "memory");
                    asm volatile("red.global.add.v2.f32 [%0], {%1,%2};"
                                 :: "l"(g_agg + (size_t)r1 * H_DIM + col),
                                    "f"(h2 * s1), "f"(h3 * s1) : "memory");
                }
            }
        }
    }
}

// ---------------------------------------------------------------------------
// layer-1 aggregation (agg init fused into gemm1 epilogue)
// ---------------------------------------------------------------------------
__global__ void k_scatter1(const int* __restrict__ edges, int E) {
    int idx = blockIdx.x * blockDim.x + threadIdx.x;   // E*32 (edge, col4)
    if (idx >= E * 32) return;
    int e = idx >> 5;
    int g = idx & 31;
    int s = edges[e];
    int d = edges[E + e];
    float norm = g_dinv[s] * g_dinv[d];
    float4 v = *reinterpret_cast<const float4*>(g_h + (size_t)s * H_DIM + g * 4);
    float* p = g_agg + (size_t)d * H_DIM + g * 4;
    asm volatile("red.global.add.v4.f32 [%0], {%1,%2,%3,%4};"
                 :: "l"(p), "f"(v.x * norm), "f"(v.y * norm),
                    "f"(v.z * norm), "f"(v.w * norm)
                 : "memory");
}

__global__ void k_bias_relu(const float* __restrict__ b1) {
    int idx = blockIdx.x * blockDim.x + threadIdx.x;   // N*32 float4 slots
    if (idx >= N_NODES * 32) return;
    int j4 = (idx & 31) * 4;
    float4 b = *reinterpret_cast<const float4*>(b1 + j4);
    float4 v = *reinterpret_cast<const float4*>(g_agg + (size_t)idx * 4);
    v.x = fmaxf(v.x + b.x, 0.f);
    v.y = fmaxf(v.y + b.y, 0.f);
    v.z = fmaxf(v.z + b.z, 0.f);
    v.w = fmaxf(v.w + b.w, 0.f);
    *reinterpret_cast<float4*>(g_h + (size_t)idx * 4) = v;
}

// ---------------------------------------------------------------------------
// GEMM2: z = h1 @ W2   [20000 x 128] @ [128 x 70] — warp per row
// ---------------------------------------------------------------------------
__global__ __launch_bounds__(256) void k_gemm2(const float* __restrict__ W2) {
    __shared__ float W2s[H_DIM * C_DIM];   // 35840 B
    int tid = threadIdx.x;
    for (int i = tid; i < H_DIM * C_DIM; i += 256) W2s[i] = W2[i];
    __syncthreads();

    int warp = tid >> 5, lane = tid & 31;
    int n = blockIdx.x * 8 + warp;
    if (n >= N_NODES) return;
    const float* hr = g_h + (size_t)n * H_DIM;

    float a0 = 0.f, a1 = 0.f, a2 = 0.f;
#pragma unroll 4
    for (int k = 0; k < H_DIM; k++) {
        float hv = __ldg(hr + k);                  // uniform per warp
        const float* wr = W2s + k * C_DIM;
        a0 += hv * wr[lane];
        a1 += hv * wr[lane + 32];
        if (lane < C_DIM - 64) a2 += hv * wr[lane + 64];
    }
    float* zr = g_z + (size_t)n * C_DIM;
    zr[lane]      = a0;
    zr[lane + 32] = a1;
    if (lane < C_DIM - 64) zr[lane + 64] = a2;
}

// ---------------------------------------------------------------------------
// layer-2 aggregation (into d_out) + softmax
// ---------------------------------------------------------------------------
__global__ void k_agg2_init(float* __restrict__ out) {
    int idx = blockIdx.x * blockDim.x + threadIdx.x;   // N*70
    if (idx >= N_NODES * C_DIM) return;
    int n = idx / C_DIM;
    float s = g_dinv[n]; s = s * s;
    out[idx] = g_z[idx] * s;
}

__global__ void k_scatter2(const int* __restrict__ edges, int E,
                           float* __restrict__ out) {
    int idx = blockIdx.x * blockDim.x + threadIdx.x;   // E*32: warp per edge
    if (idx >= E * 32) return;
    int e = idx >> 5;
    int lane = idx & 31;
    int s = edges[e];
    int d = edges[E + e];
    float norm = g_dinv[s] * g_dinv[d];
    const float* zr = g_z + (size_t)s * C_DIM;
    float* orow = out + (size_t)d * C_DIM;

    {
        float2 v = *reinterpret_cast<const float2*>(zr + 2 * lane);
        asm volatile("red.global.add.v2.f32 [%0], {%1,%2};"
                     :: "l"(orow + 2 * lane), "f"(v.x * norm), "f"(v.y * norm)
                     : "memory");
    }
    if (lane < 3) {
        float2 v = *reinterpret_cast<const float2*>(zr + 64 + 2 * lane);
        asm volatile("red.global.add.v2.f32 [%0], {%1,%2};"
                     :: "l"(orow + 64 + 2 * lane), "f"(v.x * norm), "f"(v.y * norm)
                     : "memory");
    }
}

__global__ __launch_bounds__(256) void k_softmax(const float* __restrict__ b2,
                                                 float* __restrict__ out) {
    int warp = threadIdx.x >> 5, lane = threadIdx.x & 31;
    int n = blockIdx.x * 8 + warp;
    if (n >= N_NODES) return;
    float* r = out + (size_t)n * C_DIM;

    float v0 = r[lane] + b2[lane];
    float v1 = r[lane + 32] + b2[lane + 32];
    float v2 = (lane < C_DIM - 64) ? r[lane + 64] + b2[lane + 64] : -INFINITY;

    float m = fmaxf(fmaxf(v0, v1), v2);
#pragma unroll
    for (int o = 16; o > 0; o >>= 1) m = fmaxf(m, __shfl_xor_sync(0xffffffff, m, o));

    float e0 = expf(v0 - m);
    float e1 = expf(v1 - m);
    float e2 = (lane < C_DIM - 64) ? expf(v2 - m) : 0.f;
    float s = e0 + e1 + e2;
#pragma unroll
    for (int o = 16; o > 0; o >>= 1) s += __shfl_xor_sync(0xffffffff, s, o);
    float inv = 1.f / s;

    r[lane]      = e0 * inv;
    r[lane + 32] = e1 * inv;
    if (lane < C_DIM - 64) r[lane + 64] = e2 * inv;
}

// ---------------------------------------------------------------------------
extern "C" void kernel_launch(void* const* d_in, const int* in_sizes, int n_in,
                              void* d_out, int out_size) {
    const float* x  = (const float*)d_in[0];
    const int* edges = (const int*)d_in[1];
    const float* W1 = (const float*)d_in[2];
    const float* b1 = (const float*)d_in[3];
    const float* W2 = (const float*)d_in[4];
    const float* b2 = (const float*)d_in[5];
    float* out = (float*)d_out;
    const int E = in_sizes[1] / 2;

    cudaFuncSetAttribute(k_gemm1_tc, cudaFuncAttributeMaxDynamicSharedMemorySize,
                         G1_SMEM_BYTES);

    // degree / dinv + W transpose(+tf32 round) + split-tile zero-init
    k_zero_deg<<<(N_NODES + 255) / 256, 256>>>();
    k_count_deg<<<(E + 255) / 256, 256>>>(edges, E);
    k_dinv<<<(N_NODES + 255) / 256, 256>>>();
    k_transpose<<<dim3((K_PAD + 31) / 32, H_DIM / 32), 256>>>(W1);
    k_zero_tail<<<((N_NODES - SPLIT_ROW0) * 32 + 255) / 256, 256>>>();

    // layer 1: 148 full tiles + 9 tiles split-K x16 = 292 CTAs (one wave)
    k_gemm1_tc<<<N_FULL + (157 - N_FULL) * N_SPLITS, 256, G1_SMEM_BYTES>>>(x);
    k_scatter1<<<(E * 32 + 255) / 256, 256>>>(edges, E);
    k_bias_relu<<<(N_NODES * 32 + 255) / 256, 256>>>(b1);

    // layer 2
    k_gemm2<<<(N_NODES + 7) / 8, 256>>>(W2);
    k_agg2_init<<<(N_NODES * C_DIM + 255) / 256, 256>>>(out);
    k_scatter2<<<(E * 32 + 255) / 256, 256>>>(edges, E, out);
    k_softmax<<<(N_NODES + 7) / 8, 256>>>(b2, out);
}

// round 11
// speedup vs baseline: 1.3166x; 1.3166x over previous
#include <cuda_runtime.h>
#include <math.h>
#include <stdint.h>

#define N_NODES 20000
#define K_IN    8710
#define H_DIM   128
#define C_DIM   70
#define E_MAX   640000

// ---- scratch (static device globals; no allocation allowed) ----
__device__ float g_h[(size_t)N_NODES * H_DIM];    // x@W1 (raw, pre-bias)
__device__ float g_h1[(size_t)N_NODES * H_DIM];   // relu(agg1 + b1)
__device__ float g_z[(size_t)N_NODES * C_DIM];    // h1@W2
__device__ float g_Wr[(size_t)K_IN * H_DIM];      // W1 pre-rounded to tf32
__device__ int   g_deg[N_NODES];
__device__ float g_dinv[N_NODES];
__device__ int   g_ptr[N_NODES + 1];              // CSR row ptr (by dst)
__device__ int   g_cur[N_NODES];                  // fill cursors
__device__ int2  g_csr[E_MAX];                    // {src, bitcast(norm)}

// ---------------------------------------------------------------------------
// degree / normalization / CSR build
// ---------------------------------------------------------------------------
__global__ void k_zero_deg() {
    int i = blockIdx.x * blockDim.x + threadIdx.x;
    if (i < N_NODES) g_deg[i] = 0;
}

__global__ void k_count_deg(const int* __restrict__ edges, int E) {
    int e = blockIdx.x * blockDim.x + threadIdx.x;
    if (e < E) atomicAdd(&g_deg[edges[E + e]], 1);   // dst
}

__global__ void k_dinv() {
    int i = blockIdx.x * blockDim.x + threadIdx.x;
    if (i < N_NODES) g_dinv[i] = rsqrtf((float)(g_deg[i] + 1));  // +1 self loop
}

// single-block prefix sum of g_deg -> g_ptr / g_cur  (1024 thr x 20 elems)
__global__ __launch_bounds__(1024) void k_scan() {
    __shared__ int ssum[1024];
    const int t = threadIdx.x;
    const int base = t * 20;
    int local[20];
    int s = 0;
#pragma unroll
    for (int i = 0; i < 20; i++) {
        int idx = base + i;
        local[i] = s;
        s += (idx < N_NODES) ? g_deg[idx] : 0;
    }
    ssum[t] = s;
    __syncthreads();
    for (int o = 1; o < 1024; o <<= 1) {
        int v = (t >= o) ? ssum[t - o] : 0;
        __syncthreads();
        ssum[t] += v;
        __syncthreads();
    }
    int off = ssum[t] - s;   // exclusive prefix
#pragma unroll
    for (int i = 0; i < 20; i++) {
        int idx = base + i;
        if (idx < N_NODES) {
            g_ptr[idx] = off + local[i];
            g_cur[idx] = off + local[i];
        }
    }
    if (t == 0) g_ptr[N_NODES] = ssum[1023];
}

__global__ void k_fill(const int* __restrict__ edges, int E) {
    int e = blockIdx.x * blockDim.x + threadIdx.x;
    if (e >= E) return;
    int s = edges[e];
    int d = edges[E + e];
    int pos = atomicAdd(&g_cur[d], 1);
    g_csr[pos] = make_int2(s, __float_as_int(g_dinv[s] * g_dinv[d]));
}

// ---------------------------------------------------------------------------
// pre-round W1 to tf32 (rna) so GEMM needs no in-loop cvt for B
// ---------------------------------------------------------------------------
__global__ void k_round_w(const float* __restrict__ W1) {
    int i = blockIdx.x * blockDim.x + threadIdx.x;
    if (i < K_IN * H_DIM) {
        unsigned u;
        asm("cvt.rna.tf32.f32 %0, %1;" : "=r"(u) : "f"(W1[i]));
        g_Wr[i] = __uint_as_float(u);
    }
}

// ---------------------------------------------------------------------------
// zero-init g_h rows of the split-K tiles (rows 18944..19999)
// ---------------------------------------------------------------------------
#define SPLIT_ROW0 18944
__global__ void k_zero_tail() {
    int idx = blockIdx.x * blockDim.x + threadIdx.x;   // float4 slots
    int total = (N_NODES - SPLIT_ROW0) * 32;
    if (idx >= total) return;
    *reinterpret_cast<float4*>(g_h + (size_t)SPLIT_ROW0 * H_DIM + idx * 4) =
        make_float4(0.f, 0.f, 0.f, 0.f);
}

// ---------------------------------------------------------------------------
// GEMM1, tf32 HMMA + cp.async 4-stage pipeline (known-good R8 inner loop)
//   bid 0..147   : full tiles, chunks [0,545), direct-store epilogue
//   bid 148..291 : tiles 148..156 split-K x16, red.add epilogue
// ---------------------------------------------------------------------------
#define NC_CHUNKS ((K_IN + 15) / 16)   // 545
#define G1_STAGES 4
#define G1_BM 128
#define G1_BK 16
#define N_FULL    148
#define N_SPLITS  16
#define A_STRIDE 20
#define B_STRIDE 136
#define A_WORDS (G1_BM * A_STRIDE)                   // 2560
#define STAGE_WORDS (A_WORDS + G1_BK * B_STRIDE)     // 4736
#define G1_SMEM_BYTES (G1_STAGES * STAGE_WORDS * 4)  // 75776
#define TRUNC_COMP 1.00034f

__device__ __forceinline__ unsigned smem_u32(const void* p) {
    unsigned a;
    asm("{ .reg .u64 t; cvta.to.shared.u64 t, %1; cvt.u32.u64 %0, t; }"
        : "=r"(a) : "l"(p));
    return a;
}

__global__ __launch_bounds__(256, 2) void k_gemm1_tc(const float* __restrict__ X) {
    extern __shared__ float sm[];

    const int tid  = threadIdx.x;
    const int warp = tid >> 5;
    const int lane = tid & 31;
    const int gid  = lane >> 2;
    const int tig  = lane & 3;
    const int warp_m = warp >> 1;
    const int warp_n = warp & 1;
    const unsigned sm_base = smem_u32(sm);

    int tile, c0, c_end;
    bool direct;
    if (blockIdx.x < N_FULL) {
        tile = blockIdx.x; c0 = 0; c_end = NC_CHUNKS; direct = true;
    } else {
        int t = blockIdx.x - N_FULL;
        tile = N_FULL + t / N_SPLITS;
        int s = t % N_SPLITS;
        const int base = NC_CHUNKS / N_SPLITS;
        const int rem  = NC_CHUNKS % N_SPLITS;
        c0    = s * base + (s < rem ? s : rem);
        c_end = c0 + base + (s < rem ? 1 : 0);
        direct = false;
    }
    const int m0 = tile * G1_BM;

    float acc[2][8][4];
#pragma unroll
    for (int i = 0; i < 2; i++)
#pragma unroll
        for (int j = 0; j < 8; j++)
#pragma unroll
            for (int t = 0; t < 4; t++) acc[i][j][t] = 0.f;

#define LOAD_STAGE(c)                                                             \
    {                                                                             \
        const int stg = (c) % G1_STAGES;                                          \
        const unsigned a_u = sm_base + stg * (STAGE_WORDS * 4);                   \
        const unsigned b_u = a_u + A_WORDS * 4;                                   \
        const int k0 = (c) * G1_BK;                                               \
        const bool inr = (c) < c_end;                                             \
        _Pragma("unroll")                                                         \
        for (int i = 0; i < 4; i++) {                                             \
            int p = tid + i * 256;                                                \
            int row = p >> 3;                                                     \
            int kp  = (p & 7) * 2;                                                \
            int gm = m0 + row, gk = k0 + kp;                                      \
            int ok = (inr && gm < N_NODES && gk + 1 < K_IN) ? 8 : 0;              \
            int gmc = gm < N_NODES ? gm : N_NODES - 1;                            \
            int gkc = gk + 1 < K_IN ? gk : 0;                                     \
            const float* src = X + (size_t)gmc * K_IN + gkc;                      \
            unsigned dst = a_u + (row * A_STRIDE + kp) * 4;                       \
            asm volatile("cp.async.ca.shared.global [%0], [%1], 8, %2;"           \
                         :: "r"(dst), "l"(src), "r"(ok));                         \
        }                                                                         \
        _Pragma("unroll")                                                         \
        for (int i = 0; i < 2; i++) {                                             \
            int q = tid + i * 256;                                                \
            int kr = q >> 5;                                                      \
            int nc = (q & 31) * 4;                                                \
            int gk = k0 + kr;                                                     \
            int ok = (inr && gk < K_IN) ? 16 : 0;                                 \
            int gkc = gk < K_IN ? gk : 0;                                         \
            const float* src = g_Wr + (size_t)gkc * H_DIM + nc;                   \
            unsigned dst = b_u + (kr * B_STRIDE + nc) * 4;                        \
            asm volatile("cp.async.cg.shared.global [%0], [%1], 16, %2;"          \
                         :: "r"(dst), "l"(src), "r"(ok));                         \
        }                                                                         \
        asm volatile("cp.async.commit_group;");                                   \
    }

    LOAD_STAGE(c0);
    LOAD_STAGE(c0 + 1);
    LOAD_STAGE(c0 + 2);

    for (int c = c0; c < c_end; ++c) {
        asm volatile("cp.async.wait_group %0;" :: "n"(G1_STAGES - 2));
        __syncthreads();

        LOAD_STAGE(c + G1_STAGES - 1);

        const unsigned* As = reinterpret_cast<const unsigned*>(
            sm + (c % G1_STAGES) * STAGE_WORDS);
        const unsigned* Bs = As + A_WORDS;

#pragma unroll
        for (int ks = 0; ks < 2; ks++) {
            const int kb = ks * 8;
            unsigned af[2][4];
#pragma unroll
            for (int mt = 0; mt < 2; mt++) {
                int r = warp_m * 32 + mt * 16 + gid;
                af[mt][0] = As[r * A_STRIDE + kb + tig];
                af[mt][1] = As[(r + 8) * A_STRIDE + kb + tig];
                af[mt][2] = As[r * A_STRIDE + kb + tig + 4];
                af[mt][3] = As[(r + 8) * A_STRIDE + kb + tig + 4];
            }
            unsigned bf[8][2];
#pragma unroll
            for (int nt = 0; nt < 8; nt++) {
                int nb = warp_n * 64 + nt * 8 + gid;
                bf[nt][0] = Bs[(kb + tig) * B_STRIDE + nb];
                bf[nt][1] = Bs[(kb + tig + 4) * B_STRIDE + nb];
            }
#pragma unroll
            for (int mt = 0; mt < 2; mt++)
#pragma unroll
                for (int nt = 0; nt < 8; nt++) {
                    asm volatile(
                        "mma.sync.aligned.m16n8k8.row.col.f32.tf32.tf32.f32 "
                        "{%0,%1,%2,%3}, {%4,%5,%6,%7}, {%8,%9}, {%0,%1,%2,%3};"
                        : "+f"(acc[mt][nt][0]), "+f"(acc[mt][nt][1]),
                          "+f"(acc[mt][nt][2]), "+f"(acc[mt][nt][3])
                        : "r"(af[mt][0]), "r"(af[mt][1]), "r"(af[mt][2]), "r"(af[mt][3]),
                          "r"(bf[nt][0]), "r"(bf[nt][1]));
                }
        }
    }
#undef LOAD_STAGE

    // epilogue: truncation compensation, write h only (agg is pulled later)
#pragma unroll
    for (int mt = 0; mt < 2; mt++) {
        int r0 = m0 + warp_m * 32 + mt * 16 + gid;
        int r1 = r0 + 8;
#pragma unroll
        for (int nt = 0; nt < 8; nt++) {
            int col = warp_n * 64 + nt * 8 + tig * 2;
            float h0 = acc[mt][nt][0] * TRUNC_COMP;
            float h1 = acc[mt][nt][1] * TRUNC_COMP;
            float h2 = acc[mt][nt][2] * TRUNC_COMP;
            float h3 = acc[mt][nt][3] * TRUNC_COMP;
            if (direct) {
                if (r0 < N_NODES)
                    *reinterpret_cast<float2*>(g_h + (size_t)r0 * H_DIM + col) =
                        make_float2(h0, h1);
                if (r1 < N_NODES)
                    *reinterpret_cast<float2*>(g_h + (size_t)r1 * H_DIM + col) =
                        make_float2(h2, h3);
            } else {
                if (r0 < N_NODES)
                    asm volatile("red.global.add.v2.f32 [%0], {%1,%2};"
                                 :: "l"(g_h + (size_t)r0 * H_DIM + col),
                                    "f"(h0), "f"(h1) : "memory");
                if (r1 < N_NODES)
                    asm volatile("red.global.add.v2.f32 [%0], {%1,%2};"
                                 :: "l"(g_h + (size_t)r1 * H_DIM + col),
                                    "f"(h2), "f"(h3) : "memory");
            }
        }
    }
}

// ---------------------------------------------------------------------------
// layer-1 pull aggregation: h1[n] = relu(b1 + dinv^2*h[n] + sum norm*h[src])
// warp per node, float4 per lane (128 cols)
// ---------------------------------------------------------------------------
__global__ __launch_bounds__(256) void k_agg1(const float* __restrict__ b1) {
    int warp = threadIdx.x >> 5, lane = threadIdx.x & 31;
    int n = blockIdx.x * 8 + warp;
    if (n >= N_NODES) return;

    float dv = g_dinv[n];
    float self = dv * dv;
    const float4* hn = reinterpret_cast<const float4*>(g_h + (size_t)n * H_DIM);
    float4 v = __ldg(hn + lane);
    float4 acc = make_float4(v.x * self, v.y * self, v.z * self, v.w * self);

    int j  = g_ptr[n];
    int p1 = g_ptr[n + 1];
    int2 en;
    if (j < p1) en = __ldg(&g_csr[j]);
    while (j < p1) {
        int2 cur = en;
        if (j + 1 < p1) en = __ldg(&g_csr[j + 1]);
        float nrm = __int_as_float(cur.y);
        float4 w = __ldg(reinterpret_cast<const float4*>(
                             g_h + (size_t)cur.x * H_DIM) + lane);
        acc.x += w.x * nrm; acc.y += w.y * nrm;
        acc.z += w.z * nrm; acc.w += w.w * nrm;
        ++j;
    }

    float4 b = __ldg(reinterpret_cast<const float4*>(b1) + lane);
    acc.x = fmaxf(acc.x + b.x, 0.f);
    acc.y = fmaxf(acc.y + b.y, 0.f);
    acc.z = fmaxf(acc.z + b.z, 0.f);
    acc.w = fmaxf(acc.w + b.w, 0.f);
    reinterpret_cast<float4*>(g_h1 + (size_t)n * H_DIM)[lane] = acc;
}

// ---------------------------------------------------------------------------
// GEMM2: z = h1 @ W2   [20000 x 128] @ [128 x 70] — warp per row
// ---------------------------------------------------------------------------
__global__ __launch_bounds__(256) void k_gemm2(const float* __restrict__ W2) {
    __shared__ float W2s[H_DIM * C_DIM];
    int tid = threadIdx.x;
    for (int i = tid; i < H_DIM * C_DIM; i += 256) W2s[i] = W2[i];
    __syncthreads();

    int warp = tid >> 5, lane = tid & 31;
    int n = blockIdx.x * 8 + warp;
    if (n >= N_NODES) return;
    const float* hr = g_h1 + (size_t)n * H_DIM;

    float a0 = 0.f, a1 = 0.f, a2 = 0.f;
#pragma unroll 4
    for (int k = 0; k < H_DIM; k++) {
        float hv = __ldg(hr + k);
        const float* wr = W2s + k * C_DIM;
        a0 += hv * wr[lane];
        a1 += hv * wr[lane + 32];
        if (lane < C_DIM - 64) a2 += hv * wr[lane + 64];
    }
    float* zr = g_z + (size_t)n * C_DIM;
    zr[lane]      = a0;
    zr[lane + 32] = a1;
    if (lane < C_DIM - 64) zr[lane + 64] = a2;
}

// ---------------------------------------------------------------------------
// layer-2 pull aggregation + bias + softmax -> out
// warp per node; lane l owns cols {2l,2l+1}, lanes 0..2 also {64+2l,65+2l}
// ---------------------------------------------------------------------------
__global__ __launch_bounds__(256) void k_agg2(const float* __restrict__ b2,
                                              float* __restrict__ out) {
    int warp = threadIdx.x >> 5, lane = threadIdx.x & 31;
    int n = blockIdx.x * 8 + warp;
    if (n >= N_NODES) return;
    const bool xtra = lane < 3;

    float dv = g_dinv[n];
    float self = dv * dv;
    const float* zn = g_z + (size_t)n * C_DIM;
    float2 a = *reinterpret_cast<const float2*>(zn + 2 * lane);
    a.x *= self; a.y *= self;
    float2 bacc = make_float2(0.f, 0.f);
    if (xtra) {
        float2 t = *reinterpret_cast<const float2*>(zn + 64 + 2 * lane);
        bacc.x = t.x * self; bacc.y = t.y * self;
    }

    int j  = g_ptr[n];
    int p1 = g_ptr[n + 1];
    int2 en;
    if (j < p1) en = __ldg(&g_csr[j]);
    while (j < p1) {
        int2 cur = en;
        if (j + 1 < p1) en = __ldg(&g_csr[j + 1]);
        float nrm = __int_as_float(cur.y);
        const float* zs = g_z + (size_t)cur.x * C_DIM;
        float2 v = __ldg(reinterpret_cast<const float2*>(zs + 2 * lane));
        a.x += v.x * nrm; a.y += v.y * nrm;
        if (xtra) {
            float2 t = __ldg(reinterpret_cast<const float2*>(zs + 64 + 2 * lane));
            bacc.x += t.x * nrm; bacc.y += t.y * nrm;
        }
        ++j;
    }

    // bias
    a.x += b2[2 * lane]; a.y += b2[2 * lane + 1];
    if (xtra) { bacc.x += b2[64 + 2 * lane]; bacc.y += b2[65 + 2 * lane]; }

    // softmax across the 70 owned values
    float m = fmaxf(a.x, a.y);
    if (xtra) m = fmaxf(m, fmaxf(bacc.x, bacc.y));
#pragma unroll
    for (int o = 16; o > 0; o >>= 1) m = fmaxf(m, __shfl_xor_sync(0xffffffff, m, o));

    float e0 = expf(a.x - m), e1 = expf(a.y - m);
    float e2 = 0.f, e3 = 0.f;
    if (xtra) { e2 = expf(bacc.x - m); e3 = expf(bacc.y - m); }
    float s = e0 + e1 + e2 + e3;
#pragma unroll
    for (int o = 16; o > 0; o >>= 1) s += __shfl_xor_sync(0xffffffff, s, o);
    float inv = 1.f / s;

    float* orow = out + (size_t)n * C_DIM;
    *reinterpret_cast<float2*>(orow + 2 * lane) = make_float2(e0 * inv, e1 * inv);
    if (xtra)
        *reinterpret_cast<float2*>(orow + 64 + 2 * lane) =
            make_float2(e2 * inv, e3 * inv);
}

// ---------------------------------------------------------------------------
extern "C" void kernel_launch(void* const* d_in, const int* in_sizes, int n_in,
                              void* d_out, int out_size) {
    const float* x  = (const float*)d_in[0];
    const int* edges = (const int*)d_in[1];
    const float* W1 = (const float*)d_in[2];
    const float* b1 = (const float*)d_in[3];
    const float* W2 = (const float*)d_in[4];
    const float* b2 = (const float*)d_in[5];
    float* out = (float*)d_out;
    const int E = in_sizes[1] / 2;

    cudaFuncSetAttribute(k_gemm1_tc, cudaFuncAttributeMaxDynamicSharedMemorySize,
                         G1_SMEM_BYTES);

    // degree / dinv / CSR / weight prep
    k_zero_deg<<<(N_NODES + 255) / 256, 256>>>();
    k_count_deg<<<(E + 255) / 256, 256>>>(edges, E);
    k_dinv<<<(N_NODES + 255) / 256, 256>>>();
    k_scan<<<1, 1024>>>();
    k_fill<<<(E + 255) / 256, 256>>>(edges, E);
    k_round_w<<<(K_IN * H_DIM + 255) / 256, 256>>>(W1);
    k_zero_tail<<<((N_NODES - SPLIT_ROW0) * 32 + 255) / 256, 256>>>();

    // layer 1
    k_gemm1_tc<<<N_FULL + (157 - N_FULL) * N_SPLITS, 256, G1_SMEM_BYTES>>>(x);
    k_agg1<<<(N_NODES + 7) / 8, 256>>>(b1);

    // layer 2
    k_gemm2<<<(N_NODES + 7) / 8, 256>>>(W2);
    k_agg2<<<(N_NODES + 7) / 8, 256>>>(b2, out);
}